// round 1
// baseline (speedup 1.0000x reference)
#include <cuda_runtime.h>
#include <cstdint>

#define TOKENS 8192
#define OUT_F  4096
#define IN_F   4096
#define GROUP  64
#define NGROUPS ((OUT_F * IN_F) / GROUP)   // 262144

// Scratch (static device globals: allocation-free per harness rules)
__device__ float g_w[(size_t)OUT_F * IN_F];   // dequantized W, tf32-rounded, [N][K]
__device__ float g_x[(size_t)TOKENS * IN_F];  // tf32-rounded x, [M][K]

__device__ __forceinline__ uint32_t f2tf32(float x) {
    uint32_t r;
    asm("cvt.rna.tf32.f32 %0, %1;" : "=r"(r) : "f"(x));
    return r;
}

// ---------------------------------------------------------------------------
// Kernel 1: round x to tf32 (rna) into g_x
// ---------------------------------------------------------------------------
__global__ void round_x_kernel(const float* __restrict__ x) {
    int i = blockIdx.x * blockDim.x + threadIdx.x;  // one float4 per thread
    float4 v = ((const float4*)x)[i];
    float4 o;
    o.x = __uint_as_float(f2tf32(v.x));
    o.y = __uint_as_float(f2tf32(v.y));
    o.z = __uint_as_float(f2tf32(v.z));
    o.w = __uint_as_float(f2tf32(v.w));
    ((float4*)g_x)[i] = o;
}

// ---------------------------------------------------------------------------
// Kernel 2: unpack 4-bit + dequant + tf32-round into g_w
// Group g covers row g/64, cols (g%64)*64 .. +63  (flat idx == g*64+j)
// hi nibble -> groups [0, G/2), lo nibble -> groups [G/2, G)
// ---------------------------------------------------------------------------
__global__ void dequant_kernel(const int* __restrict__ Wq,
                               const float* __restrict__ scale,
                               const float* __restrict__ zero) {
    int idx = blockIdx.x * blockDim.x + threadIdx.x;  // 0 .. OUT_F*IN_F-1
    int g = idx >> 6;
    int j = idx & 63;
    const int half = NGROUPS / 2;
    int pg = (g < half) ? g : (g - half);
    int q  = Wq[(size_t)pg * GROUP + j];
    int nib = (g < half) ? ((q >> 4) & 0xF) : (q & 0xF);
    float w = ((float)nib - zero[g]) * scale[g];
    g_w[idx] = __uint_as_float(f2tf32(w));
}

// ---------------------------------------------------------------------------
// Kernel 3: GEMM out[M,N] = g_x[M,K] * g_w[N,K]^T + bias
// 128x128x32 CTA tile, 3-stage cp.async pipeline, 8 warps (2m x 4n),
// warp tile 64x32, mma.sync m16n8k8 tf32.
// ---------------------------------------------------------------------------
#define BM 128
#define BN 128
#define BK 32
#define STAGES 3
#define SST 36                         // padded row stride (floats): conflict-free frags
#define STAGE_FLOATS ((BM + BN) * SST) // 9216 floats / stage

__device__ __forceinline__ void cp_async16(void* smem_ptr, const void* gmem_ptr) {
    uint32_t s = (uint32_t)__cvta_generic_to_shared(smem_ptr);
    asm volatile("cp.async.cg.shared.global [%0], [%1], 16;" :: "r"(s), "l"(gmem_ptr));
}

__global__ __launch_bounds__(256, 1)
void gemm_kernel(const float* __restrict__ bias, float* __restrict__ out) {
    extern __shared__ float smem[];
    const int tid  = threadIdx.x;
    const int lane = tid & 31;
    const int wid  = tid >> 5;
    const int wm   = wid >> 2;   // 0..1  (64 rows each)
    const int wn   = wid & 3;    // 0..3  (32 cols each)
    const int bm0  = blockIdx.y * BM;
    const int bn0  = blockIdx.x * BN;
    const int lr   = lane >> 2;  // 0..7
    const int lc   = lane & 3;   // 0..3

    float acc[4][4][4];
    #pragma unroll
    for (int a = 0; a < 4; a++)
        #pragma unroll
        for (int b = 0; b < 4; b++)
            #pragma unroll
            for (int c = 0; c < 4; c++) acc[a][b][c] = 0.0f;

    const int KT = IN_F / BK;  // 128

    auto issue = [&](int kt) {
        float* sA = smem + (kt % STAGES) * STAGE_FLOATS;
        float* sB = sA + BM * SST;
        int k0 = kt * BK;
        #pragma unroll
        for (int i = 0; i < 4; i++) {           // 1024 chunks A / 256 threads
            int c  = tid + i * 256;
            int r  = c >> 3;
            int c4 = (c & 7) * 4;
            cp_async16(sA + r * SST + c4, g_x + (size_t)(bm0 + r) * IN_F + k0 + c4);
        }
        #pragma unroll
        for (int i = 0; i < 4; i++) {           // 1024 chunks B
            int c  = tid + i * 256;
            int r  = c >> 3;
            int c4 = (c & 7) * 4;
            cp_async16(sB + r * SST + c4, g_w + (size_t)(bn0 + r) * IN_F + k0 + c4);
        }
        asm volatile("cp.async.commit_group;");
    };

    issue(0);
    issue(1);

    for (int kt = 0; kt < KT; kt++) {
        asm volatile("cp.async.wait_group %0;" :: "n"(STAGES - 2));
        __syncthreads();
        if (kt + STAGES - 1 < KT) issue(kt + STAGES - 1);

        const float* sA = smem + (kt % STAGES) * STAGE_FLOATS;
        const float* sB = sA + BM * SST;

        #pragma unroll
        for (int kk = 0; kk < 4; kk++) {        // 4 x k8 steps per BK=32
            int k0 = kk * 8;
            uint32_t af[4][4], bf[4][2];
            #pragma unroll
            for (int mt = 0; mt < 4; mt++) {
                int rb = wm * 64 + mt * 16;
                af[mt][0] = __float_as_uint(sA[(rb + lr)     * SST + k0 + lc]);
                af[mt][1] = __float_as_uint(sA[(rb + 8 + lr) * SST + k0 + lc]);
                af[mt][2] = __float_as_uint(sA[(rb + lr)     * SST + k0 + 4 + lc]);
                af[mt][3] = __float_as_uint(sA[(rb + 8 + lr) * SST + k0 + 4 + lc]);
            }
            #pragma unroll
            for (int nt = 0; nt < 4; nt++) {
                int nb = wn * 32 + nt * 8;
                bf[nt][0] = __float_as_uint(sB[(nb + lr) * SST + k0 + lc]);
                bf[nt][1] = __float_as_uint(sB[(nb + lr) * SST + k0 + 4 + lc]);
            }
            #pragma unroll
            for (int mt = 0; mt < 4; mt++)
                #pragma unroll
                for (int nt = 0; nt < 4; nt++)
                    asm volatile(
                        "mma.sync.aligned.m16n8k8.row.col.f32.tf32.tf32.f32 "
                        "{%0,%1,%2,%3}, {%4,%5,%6,%7}, {%8,%9}, {%0,%1,%2,%3};"
                        : "+f"(acc[mt][nt][0]), "+f"(acc[mt][nt][1]),
                          "+f"(acc[mt][nt][2]), "+f"(acc[mt][nt][3])
                        : "r"(af[mt][0]), "r"(af[mt][1]), "r"(af[mt][2]), "r"(af[mt][3]),
                          "r"(bf[nt][0]), "r"(bf[nt][1]));
        }
    }

    // Epilogue: +bias, float2 stores
    #pragma unroll
    for (int mt = 0; mt < 4; mt++) {
        #pragma unroll
        for (int nt = 0; nt < 4; nt++) {
            int r = bm0 + wm * 64 + mt * 16 + lr;
            int c = bn0 + wn * 32 + nt * 8 + lc * 2;
            float b0 = bias[c], b1 = bias[c + 1];
            float2 v0 = make_float2(acc[mt][nt][0] + b0, acc[mt][nt][1] + b1);
            float2 v1 = make_float2(acc[mt][nt][2] + b0, acc[mt][nt][3] + b1);
            *(float2*)&out[(size_t)r       * OUT_F + c] = v0;
            *(float2*)&out[(size_t)(r + 8) * OUT_F + c] = v1;
        }
    }
}

// ---------------------------------------------------------------------------
// Launch
// ---------------------------------------------------------------------------
extern "C" void kernel_launch(void* const* d_in, const int* in_sizes, int n_in,
                              void* d_out, int out_size) {
    const float* x     = (const float*)d_in[0];
    const int*   Wq    = (const int*)d_in[1];
    const float* scale = (const float*)d_in[2];
    const float* zero  = (const float*)d_in[3];
    const float* bias  = (const float*)d_in[4];
    float* out = (float*)d_out;

    round_x_kernel<<<(TOKENS * IN_F / 4) / 256, 256>>>(x);
    dequant_kernel<<<(OUT_F * IN_F) / 256, 256>>>(Wq, scale, zero);

    int smem_bytes = STAGES * STAGE_FLOATS * 4;  // 110592 bytes
    cudaFuncSetAttribute(gemm_kernel, cudaFuncAttributeMaxDynamicSharedMemorySize, smem_bytes);
    dim3 grid(OUT_F / BN, TOKENS / BM);  // (32, 64)
    gemm_kernel<<<grid, 256, smem_bytes>>>(bias, out);
}

// round 3
// speedup vs baseline: 4.4021x; 4.4021x over previous
#include <cuda_runtime.h>
#include <cuda_fp16.h>
#include <cstdint>

#define TOKENS 8192
#define OUT_F  4096
#define IN_F   4096
#define GROUP  64
#define NGROUPS ((OUT_F * IN_F) / GROUP)   // 262144

#define BM 128
#define BN 256
#define BK 32
#define NKC (IN_F / BK)                    // 128 K-chunks
#define STAGES 6
#define ROWB 80                            // smem/gmem row stride in bytes (40 halfs)
#define A_CHUNK_HALFS (BM * 40)            // 5120  (10240 B)
#define B_CHUNK_HALFS (BN * 40)            // 10240 (20480 B)
#define A_BYTES (BM * ROWB)                // 10240
#define B_BYTES (BN * ROWB)                // 20480
#define STAGE_BYTES (A_BYTES + B_BYTES)    // 30720
#define CTRL_BYTES 1024
#define SMEM_TOTAL (CTRL_BYTES + STAGES * STAGE_BYTES)  // 185344

// Padded, tile-contiguous fp16 scratch (device globals: allocation-free).
// g_x chunk (mt, kc): 128 rows x 40 halfs, contiguous. base = (mt*NKC+kc)*A_CHUNK_HALFS
// g_w chunk (nt, kc): 256 rows x 40 halfs.             base = (nt*NKC+kc)*B_CHUNK_HALFS
__device__ __half g_x[(size_t)(TOKENS / BM) * NKC * A_CHUNK_HALFS];  // 84 MB
__device__ __half g_w[(size_t)(OUT_F / BN) * NKC * B_CHUNK_HALFS];   // 42 MB

// ---------------------------------------------------------------------------
// Prep 1: fp16-convert x into padded tiled g_x
// ---------------------------------------------------------------------------
__global__ void round_x_kernel(const float* __restrict__ x) {
    int i = blockIdx.x * blockDim.x + threadIdx.x;   // one float4 per thread
    float4 v = ((const float4*)x)[i];
    union { __half2 h[2]; uint2 u; } pk;
    pk.h[0] = __floats2half2_rn(v.x, v.y);
    pk.h[1] = __floats2half2_rn(v.z, v.w);
    int m  = i >> 10;                 // 1024 float4 per row
    int k  = (i & 1023) << 2;
    int mt = m >> 7, r = m & 127;
    int kc = k >> 5, c = k & 31;
    __half* dst = g_x + (size_t)(mt * NKC + kc) * A_CHUNK_HALFS + r * 40 + c;
    *(uint2*)dst = pk.u;
}

// ---------------------------------------------------------------------------
// Prep 2: unpack 4-bit + dequant + fp16 into padded tiled g_w
// flat idx = n*4096 + k ; group g = idx>>6 ; j = idx&63
// ---------------------------------------------------------------------------
__global__ void dequant_kernel(const int* __restrict__ Wq,
                               const float* __restrict__ scale,
                               const float* __restrict__ zero) {
    int t = blockIdx.x * blockDim.x + threadIdx.x;   // 4 elements per thread
    int idx = t << 2;
    int g = idx >> 6;
    int j = idx & 63;
    const int half_g = NGROUPS / 2;
    int pg = (g < half_g) ? g : (g - half_g);
    int4 q = *(const int4*)(Wq + (size_t)pg * GROUP + j);
    float z = zero[g], s = scale[g];
    float4 o;
    if (g < half_g) {
        o.x = ((float)((q.x >> 4) & 0xF) - z) * s;
        o.y = ((float)((q.y >> 4) & 0xF) - z) * s;
        o.z = ((float)((q.z >> 4) & 0xF) - z) * s;
        o.w = ((float)((q.w >> 4) & 0xF) - z) * s;
    } else {
        o.x = ((float)(q.x & 0xF) - z) * s;
        o.y = ((float)(q.y & 0xF) - z) * s;
        o.z = ((float)(q.z & 0xF) - z) * s;
        o.w = ((float)(q.w & 0xF) - z) * s;
    }
    union { __half2 h[2]; uint2 u; } pk;
    pk.h[0] = __floats2half2_rn(o.x, o.y);
    pk.h[1] = __floats2half2_rn(o.z, o.w);
    int n  = idx >> 12;
    int k  = idx & 4095;
    int nt = n >> 8, r = n & 255;
    int kc = k >> 5, c = k & 31;
    __half* dst = g_w + (size_t)(nt * NKC + kc) * B_CHUNK_HALFS + r * 40 + c;
    *(uint2*)dst = pk.u;
}

// ---------------------------------------------------------------------------
// sm_90-base async helpers (NO tcgen05 — rejected on this toolchain target)
// ---------------------------------------------------------------------------
__device__ __forceinline__ void mbar_init(uint32_t mbar, uint32_t cnt) {
    asm volatile("mbarrier.init.shared.b64 [%0], %1;" :: "r"(mbar), "r"(cnt) : "memory");
}
__device__ __forceinline__ void mbar_expect_tx(uint32_t mbar, uint32_t bytes) {
    asm volatile("mbarrier.arrive.expect_tx.shared.b64 _, [%0], %1;"
                 :: "r"(mbar), "r"(bytes) : "memory");
}
__device__ __forceinline__ void mbar_wait(uint32_t mbar, uint32_t parity) {
    asm volatile(
        "{\n\t.reg .pred P;\n\t"
        "WL_%=:\n\t"
        "mbarrier.try_wait.parity.shared.b64 P, [%0], %1, 0x989680;\n\t"
        "@!P bra WL_%=;\n\t}"
        :: "r"(mbar), "r"(parity) : "memory");
}
__device__ __forceinline__ void bulk_g2s(uint32_t dst, const void* src,
                                         uint32_t bytes, uint32_t mbar) {
    asm volatile(
        "cp.async.bulk.shared::cluster.global.mbarrier::complete_tx::bytes "
        "[%0], [%1], %2, [%3];"
        :: "r"(dst), "l"(src), "r"(bytes), "r"(mbar) : "memory");
}
__device__ __forceinline__ void ldsm_x4(uint32_t* r, uint32_t addr) {
    asm volatile("ldmatrix.sync.aligned.m8n8.x4.shared.b16 {%0,%1,%2,%3}, [%4];"
                 : "=r"(r[0]), "=r"(r[1]), "=r"(r[2]), "=r"(r[3]) : "r"(addr));
}
__device__ __forceinline__ void mma16816(float* c, const uint32_t* a, const uint32_t* b) {
    asm volatile(
        "mma.sync.aligned.m16n8k16.row.col.f32.f16.f16.f32 "
        "{%0,%1,%2,%3}, {%4,%5,%6,%7}, {%8,%9}, {%0,%1,%2,%3};"
        : "+f"(c[0]), "+f"(c[1]), "+f"(c[2]), "+f"(c[3])
        : "r"(a[0]), "r"(a[1]), "r"(a[2]), "r"(a[3]), "r"(b[0]), "r"(b[1]));
}

// ---------------------------------------------------------------------------
// GEMM: out[M,N] = x[M,K] * W[N,K]^T + bias.  128x256 tile, fp16 mma.sync,
// 1-D bulk-TMA producer (thread 0), 6-stage mbarrier pipeline.
// ---------------------------------------------------------------------------
__global__ __launch_bounds__(256, 1)
void gemm_kernel(const float* __restrict__ bias, float* __restrict__ out) {
    extern __shared__ __align__(1024) char smem[];
    uint32_t sb = (uint32_t)__cvta_generic_to_shared(smem);
    const int tid  = threadIdx.x;
    const int lane = tid & 31;
    const int wid  = tid >> 5;
    const int wm   = wid >> 2;            // 0..1  (64 rows)
    const int wn   = wid & 3;             // 0..3  (64 cols)
    const int bn0  = blockIdx.x * BN;
    const int bm0  = blockIdx.y * BM;

    // full[s] mbarrier at sb + s*8
    if (tid == 0) {
        #pragma unroll
        for (int s = 0; s < STAGES; s++) mbar_init(sb + s * 8, 1);
        asm volatile("fence.proxy.async.shared::cta;" ::: "memory");
    }
    __syncthreads();

    const __half* Asrc = g_x + (size_t)blockIdx.y * NKC * A_CHUNK_HALFS;
    const __half* Bsrc = g_w + (size_t)blockIdx.x * NKC * B_CHUNK_HALFS;

    if (tid == 0) {
        #pragma unroll
        for (int s = 0; s < STAGES - 1; s++) {
            mbar_expect_tx(sb + s * 8, STAGE_BYTES);
            uint32_t st = sb + CTRL_BYTES + s * STAGE_BYTES;
            bulk_g2s(st,           Asrc + (size_t)s * A_CHUNK_HALFS, A_BYTES, sb + s * 8);
            bulk_g2s(st + A_BYTES, Bsrc + (size_t)s * B_CHUNK_HALFS, B_BYTES, sb + s * 8);
        }
    }

    float acc[4][8][4];
    #pragma unroll
    for (int a = 0; a < 4; a++)
        #pragma unroll
        for (int b = 0; b < 8; b++)
            #pragma unroll
            for (int c = 0; c < 4; c++) acc[a][b][c] = 0.0f;

    // ldmatrix lane address components
    const int a_row = (lane & 15);
    const int a_col = (lane >> 4) * 16;                         // bytes
    const int b_row = (lane & 7) + ((lane & 16) >> 1);          // n within 16
    const int b_col = ((lane >> 3) & 1) * 16;                   // bytes

    int slot = 0, ph = 0;
    for (int c = 0; c < NKC; c++) {
        mbar_wait(sb + slot * 8, ph);

        uint32_t aBase = sb + CTRL_BYTES + slot * STAGE_BYTES;
        uint32_t bBase = aBase + A_BYTES;

        #pragma unroll
        for (int ks = 0; ks < 2; ks++) {
            uint32_t af[4][4];
            #pragma unroll
            for (int mt = 0; mt < 4; mt++)
                ldsm_x4(af[mt], aBase + (uint32_t)(wm * 64 + mt * 16 + a_row) * ROWB
                                + ks * 32 + a_col);
            uint32_t bf[8][2];
            #pragma unroll
            for (int bt = 0; bt < 4; bt++) {
                uint32_t r4[4];
                ldsm_x4(r4, bBase + (uint32_t)(wn * 64 + bt * 16 + b_row) * ROWB
                             + ks * 32 + b_col);
                bf[2 * bt][0] = r4[0]; bf[2 * bt][1] = r4[1];
                bf[2 * bt + 1][0] = r4[2]; bf[2 * bt + 1][1] = r4[3];
            }
            #pragma unroll
            for (int mt = 0; mt < 4; mt++)
                #pragma unroll
                for (int nt = 0; nt < 8; nt++)
                    mma16816(acc[mt][nt], af[mt], bf[nt]);
        }

        __syncthreads();   // all warps done reading the oldest stage
        if (tid == 0 && c + STAGES - 1 < NKC) {
            int kc2 = c + STAGES - 1;
            int s2  = kc2 % STAGES;
            mbar_expect_tx(sb + s2 * 8, STAGE_BYTES);
            uint32_t st = sb + CTRL_BYTES + s2 * STAGE_BYTES;
            bulk_g2s(st,           Asrc + (size_t)kc2 * A_CHUNK_HALFS, A_BYTES, sb + s2 * 8);
            bulk_g2s(st + A_BYTES, Bsrc + (size_t)kc2 * B_CHUNK_HALFS, B_BYTES, sb + s2 * 8);
        }
        if (++slot == STAGES) { slot = 0; ph ^= 1; }
    }

    // Epilogue: +bias, float2 stores
    const int lr = lane >> 2;
    const int lc = lane & 3;
    #pragma unroll
    for (int mt = 0; mt < 4; mt++) {
        #pragma unroll
        for (int nt = 0; nt < 8; nt++) {
            int row = bm0 + wm * 64 + mt * 16 + lr;
            int col = bn0 + wn * 64 + nt * 8 + lc * 2;
            float b0 = __ldg(&bias[col]), b1 = __ldg(&bias[col + 1]);
            *(float2*)&out[(size_t)row * OUT_F + col] =
                make_float2(acc[mt][nt][0] + b0, acc[mt][nt][1] + b1);
            *(float2*)&out[(size_t)(row + 8) * OUT_F + col] =
                make_float2(acc[mt][nt][2] + b0, acc[mt][nt][3] + b1);
        }
    }
}

// ---------------------------------------------------------------------------
// Launch
// ---------------------------------------------------------------------------
extern "C" void kernel_launch(void* const* d_in, const int* in_sizes, int n_in,
                              void* d_out, int out_size) {
    const float* x     = (const float*)d_in[0];
    const int*   Wq    = (const int*)d_in[1];
    const float* scale = (const float*)d_in[2];
    const float* zero  = (const float*)d_in[3];
    const float* bias  = (const float*)d_in[4];
    float* out = (float*)d_out;

    round_x_kernel<<<(TOKENS * IN_F / 4) / 256, 256>>>(x);
    dequant_kernel<<<(OUT_F * IN_F / 4) / 256, 256>>>(Wq, scale, zero);

    cudaFuncSetAttribute(gemm_kernel, cudaFuncAttributeMaxDynamicSharedMemorySize, SMEM_TOTAL);
    dim3 grid(OUT_F / BN, TOKENS / BM);   // (16, 64)
    gemm_kernel<<<grid, 256, SMEM_TOTAL>>>(bias, out);
}

// round 5
// speedup vs baseline: 4.8042x; 1.0914x over previous
#include <cuda_runtime.h>
#include <cuda_fp16.h>
#include <cstdint>

#define TOKENS 8192
#define OUT_F  4096
#define IN_F   4096
#define GROUP  64
#define NGROUPS ((OUT_F * IN_F) / GROUP)   // 262144

#define BM 128
#define BN 256
#define BK 64
#define NKC (IN_F / BK)                    // 64 K-chunks
#define STAGES 3
#define ROWH 72                            // halfs per row (64 data + 8 pad)
#define ROWB 144                           // bytes per row
#define A_CHUNK_HALFS (BM * ROWH)          // 9216
#define B_CHUNK_HALFS (BN * ROWH)          // 18432
#define A_BYTES (BM * ROWB)                // 18432
#define B_BYTES (BN * ROWB)                // 36864
#define STAGE_BYTES (A_BYTES + B_BYTES)    // 55296
#define CTRL_BYTES 1024
#define SMEM_TOTAL (CTRL_BYTES + STAGES * STAGE_BYTES)  // 166912

// Padded, tile-contiguous fp16 scratch (device globals: allocation-free).
__device__ __half g_x[(size_t)(TOKENS / BM) * NKC * A_CHUNK_HALFS];  // ~75 MB
__device__ __half g_w[(size_t)(OUT_F / BN) * NKC * B_CHUNK_HALFS];   // ~38 MB

// ---------------------------------------------------------------------------
// Fused prep: blocks [0, XB) convert x; blocks [XB, XB+WB) dequant W.
// ---------------------------------------------------------------------------
#define XB ((TOKENS * IN_F / 4) / 256)     // 32768
#define WB ((OUT_F * IN_F / 4) / 256)      // 16384

__global__ void prep_kernel(const float* __restrict__ x,
                            const int* __restrict__ Wq,
                            const float* __restrict__ scale,
                            const float* __restrict__ zero) {
    if (blockIdx.x < XB) {
        int i = blockIdx.x * 256 + threadIdx.x;          // one float4 of x
        float4 v = ((const float4*)x)[i];
        union { __half2 h[2]; uint2 u; } pk;
        pk.h[0] = __floats2half2_rn(v.x, v.y);
        pk.h[1] = __floats2half2_rn(v.z, v.w);
        int m  = i >> 10;                 // 1024 float4 per row
        int k  = (i & 1023) << 2;
        int mt = m >> 7, r = m & 127;
        int kc = k >> 6, c = k & 63;
        __half* dst = g_x + (size_t)(mt * NKC + kc) * A_CHUNK_HALFS + r * ROWH + c;
        *(uint2*)dst = pk.u;
    } else {
        int t = (blockIdx.x - XB) * 256 + threadIdx.x;   // 4 elements of W
        int idx = t << 2;
        int g = idx >> 6;
        int j = idx & 63;
        const int half_g = NGROUPS / 2;
        int pg = (g < half_g) ? g : (g - half_g);
        int4 q = *(const int4*)(Wq + (size_t)pg * GROUP + j);
        float z = zero[g], s = scale[g];
        float4 o;
        if (g < half_g) {
            o.x = ((float)((q.x >> 4) & 0xF) - z) * s;
            o.y = ((float)((q.y >> 4) & 0xF) - z) * s;
            o.z = ((float)((q.z >> 4) & 0xF) - z) * s;
            o.w = ((float)((q.w >> 4) & 0xF) - z) * s;
        } else {
            o.x = ((float)(q.x & 0xF) - z) * s;
            o.y = ((float)(q.y & 0xF) - z) * s;
            o.z = ((float)(q.z & 0xF) - z) * s;
            o.w = ((float)(q.w & 0xF) - z) * s;
        }
        union { __half2 h[2]; uint2 u; } pk;
        pk.h[0] = __floats2half2_rn(o.x, o.y);
        pk.h[1] = __floats2half2_rn(o.z, o.w);
        int n  = idx >> 12;
        int k  = idx & 4095;
        int nt = n >> 8, r = n & 255;
        int kc = k >> 6, c = k & 63;
        __half* dst = g_w + (size_t)(nt * NKC + kc) * B_CHUNK_HALFS + r * ROWH + c;
        *(uint2*)dst = pk.u;
    }
}

// ---------------------------------------------------------------------------
// sm_90-base async helpers (NO tcgen05 — ptxas target is sm_103, not sm_103a)
// ---------------------------------------------------------------------------
__device__ __forceinline__ void mbar_init(uint32_t mbar, uint32_t cnt) {
    asm volatile("mbarrier.init.shared.b64 [%0], %1;" :: "r"(mbar), "r"(cnt) : "memory");
}
__device__ __forceinline__ void mbar_expect_tx(uint32_t mbar, uint32_t bytes) {
    asm volatile("mbarrier.arrive.expect_tx.shared.b64 _, [%0], %1;"
                 :: "r"(mbar), "r"(bytes) : "memory");
}
__device__ __forceinline__ void mbar_wait(uint32_t mbar, uint32_t parity) {
    asm volatile(
        "{\n\t.reg .pred P;\n\t"
        "WL_%=:\n\t"
        "mbarrier.try_wait.parity.shared.b64 P, [%0], %1, 0x989680;\n\t"
        "@!P bra WL_%=;\n\t}"
        :: "r"(mbar), "r"(parity) : "memory");
}
__device__ __forceinline__ void bulk_g2s(uint32_t dst, const void* src,
                                         uint32_t bytes, uint32_t mbar) {
    asm volatile(
        "cp.async.bulk.shared::cluster.global.mbarrier::complete_tx::bytes "
        "[%0], [%1], %2, [%3];"
        :: "r"(dst), "l"(src), "r"(bytes), "r"(mbar) : "memory");
}
__device__ __forceinline__ void ldsm_x4(uint32_t* r, uint32_t addr) {
    asm volatile("ldmatrix.sync.aligned.m8n8.x4.shared.b16 {%0,%1,%2,%3}, [%4];"
                 : "=r"(r[0]), "=r"(r[1]), "=r"(r[2]), "=r"(r[3]) : "r"(addr));
}
__device__ __forceinline__ void mma16816(float* c, const uint32_t* a, const uint32_t* b) {
    asm volatile(
        "mma.sync.aligned.m16n8k16.row.col.f32.f16.f16.f32 "
        "{%0,%1,%2,%3}, {%4,%5,%6,%7}, {%8,%9}, {%0,%1,%2,%3};"
        : "+f"(c[0]), "+f"(c[1]), "+f"(c[2]), "+f"(c[3])
        : "r"(a[0]), "r"(a[1]), "r"(a[2]), "r"(a[3]), "r"(b[0]), "r"(b[1]));
}

// ---------------------------------------------------------------------------
// GEMM: out[M,N] = x[M,K] * W[N,K]^T + bias.  128x256x64 tile, fp16 mma.sync,
// 1-D bulk-TMA producer (thread 0), 3-stage mbarrier pipeline.
// ---------------------------------------------------------------------------
__global__ __launch_bounds__(256, 1)
void gemm_kernel(const float* __restrict__ bias, float* __restrict__ out) {
    extern __shared__ __align__(1024) char smem[];
    uint32_t sb = (uint32_t)__cvta_generic_to_shared(smem);
    const int tid  = threadIdx.x;
    const int lane = tid & 31;
    const int wid  = tid >> 5;
    const int wm   = wid >> 2;            // 0..1  (64 rows)
    const int wn   = wid & 3;             // 0..3  (64 cols)
    const int bn0  = blockIdx.x * BN;
    const int bm0  = blockIdx.y * BM;

    if (tid == 0) {
        #pragma unroll
        for (int s = 0; s < STAGES; s++) mbar_init(sb + s * 8, 1);
        asm volatile("fence.proxy.async.shared::cta;" ::: "memory");
    }
    __syncthreads();

    const __half* Asrc = g_x + (size_t)blockIdx.y * NKC * A_CHUNK_HALFS;
    const __half* Bsrc = g_w + (size_t)blockIdx.x * NKC * B_CHUNK_HALFS;

    if (tid == 0) {
        #pragma unroll
        for (int s = 0; s < STAGES - 1; s++) {
            mbar_expect_tx(sb + s * 8, STAGE_BYTES);
            uint32_t st = sb + CTRL_BYTES + s * STAGE_BYTES;
            bulk_g2s(st,           Asrc + (size_t)s * A_CHUNK_HALFS, A_BYTES, sb + s * 8);
            bulk_g2s(st + A_BYTES, Bsrc + (size_t)s * B_CHUNK_HALFS, B_BYTES, sb + s * 8);
        }
    }

    float acc[4][8][4];
    #pragma unroll
    for (int a = 0; a < 4; a++)
        #pragma unroll
        for (int b = 0; b < 8; b++)
            #pragma unroll
            for (int c = 0; c < 4; c++) acc[a][b][c] = 0.0f;

    // ldmatrix lane address components
    const int a_row = (lane & 15);
    const int a_col = (lane >> 4) * 16;                   // bytes
    const int b_row = (lane & 7) + ((lane & 16) >> 1);
    const int b_col = ((lane >> 3) & 1) * 16;             // bytes

    int slot = 0, ph = 0;
    for (int c = 0; c < NKC; c++) {
        mbar_wait(sb + slot * 8, ph);

        uint32_t aBase = sb + CTRL_BYTES + slot * STAGE_BYTES;
        uint32_t bBase = aBase + A_BYTES;

        #pragma unroll
        for (int ks = 0; ks < 4; ks++) {                  // 4 x k16 per BK=64
            uint32_t af[4][4];
            #pragma unroll
            for (int mt = 0; mt < 4; mt++)
                ldsm_x4(af[mt], aBase + (uint32_t)(wm * 64 + mt * 16 + a_row) * ROWB
                                + ks * 32 + a_col);
            uint32_t bf[8][2];
            #pragma unroll
            for (int bt = 0; bt < 4; bt++) {
                uint32_t r4[4];
                ldsm_x4(r4, bBase + (uint32_t)(wn * 64 + bt * 16 + b_row) * ROWB
                             + ks * 32 + b_col);
                bf[2 * bt][0] = r4[0]; bf[2 * bt][1] = r4[1];
                bf[2 * bt + 1][0] = r4[2]; bf[2 * bt + 1][1] = r4[3];
            }
            #pragma unroll
            for (int mt = 0; mt < 4; mt++)
                #pragma unroll
                for (int nt = 0; nt < 8; nt++)
                    mma16816(acc[mt][nt], af[mt], bf[nt]);
        }

        __syncthreads();   // all warps done reading the oldest stage
        if (tid == 0 && c + STAGES - 1 < NKC) {
            int kc2 = c + STAGES - 1;
            int s2  = kc2 % STAGES;
            mbar_expect_tx(sb + s2 * 8, STAGE_BYTES);
            uint32_t st = sb + CTRL_BYTES + s2 * STAGE_BYTES;
            bulk_g2s(st,           Asrc + (size_t)kc2 * A_CHUNK_HALFS, A_BYTES, sb + s2 * 8);
            bulk_g2s(st + A_BYTES, Bsrc + (size_t)kc2 * B_CHUNK_HALFS, B_BYTES, sb + s2 * 8);
        }
        if (++slot == STAGES) { slot = 0; ph ^= 1; }
    }

    // Epilogue: +bias, float2 stores
    const int lr = lane >> 2;
    const int lc = lane & 3;
    #pragma unroll
    for (int mt = 0; mt < 4; mt++) {
        #pragma unroll
        for (int nt = 0; nt < 8; nt++) {
            int row = bm0 + wm * 64 + mt * 16 + lr;
            int col = bn0 + wn * 64 + nt * 8 + lc * 2;
            float b0 = __ldg(&bias[col]), b1 = __ldg(&bias[col + 1]);
            *(float2*)&out[(size_t)row * OUT_F + col] =
                make_float2(acc[mt][nt][0] + b0, acc[mt][nt][1] + b1);
            *(float2*)&out[(size_t)(row + 8) * OUT_F + col] =
                make_float2(acc[mt][nt][2] + b0, acc[mt][nt][3] + b1);
        }
    }
}

// ---------------------------------------------------------------------------
// Launch
// ---------------------------------------------------------------------------
extern "C" void kernel_launch(void* const* d_in, const int* in_sizes, int n_in,
                              void* d_out, int out_size) {
    const float* x     = (const float*)d_in[0];
    const int*   Wq    = (const int*)d_in[1];
    const float* scale = (const float*)d_in[2];
    const float* zero  = (const float*)d_in[3];
    const float* bias  = (const float*)d_in[4];
    float* out = (float*)d_out;

    prep_kernel<<<XB + WB, 256>>>(x, Wq, scale, zero);

    cudaFuncSetAttribute(gemm_kernel, cudaFuncAttributeMaxDynamicSharedMemorySize, SMEM_TOTAL);
    dim3 grid(OUT_F / BN, TOKENS / BM);   // (16, 64)
    gemm_kernel<<<grid, 256, SMEM_TOTAL>>>(bias, out);
}

// round 7
// speedup vs baseline: 5.1021x; 1.0620x over previous
#include <cuda_runtime.h>
#include <cuda_fp16.h>
#include <cstdint>

#define TOKENS 8192
#define OUT_F  4096
#define IN_F   4096
#define GROUP  64
#define NGROUPS ((OUT_F * IN_F) / GROUP)   // 262144

#define BM 128
#define BN 256
#define BK 64
#define NKC (IN_F / BK)                    // 64 K-chunks
#define STAGES 3
#define ROWH 72                            // halfs per row (64 data + 8 pad)
#define ROWB 144                           // bytes per row
#define A_CHUNK_HALFS (BM * ROWH)          // 9216
#define B_CHUNK_HALFS (BN * ROWH)          // 18432
#define A_BYTES (BM * ROWB)                // 18432
#define B_BYTES (BN * ROWB)                // 36864
#define STAGE_BYTES (A_BYTES + B_BYTES)    // 55296
#define CTRL_BYTES 1024
#define SMEM_TOTAL (CTRL_BYTES + STAGES * STAGE_BYTES)  // 166912

// Padded, tile-contiguous fp16 scratch (device globals: allocation-free).
__device__ __half g_x[(size_t)(TOKENS / BM) * NKC * A_CHUNK_HALFS];  // ~75 MB
__device__ __half g_w[(size_t)(OUT_F / BN) * NKC * B_CHUNK_HALFS];   // ~38 MB

// ---------------------------------------------------------------------------
// Fused prep: blocks [0, XB) convert x; blocks [XB, XB+WB) dequant W.
// ---------------------------------------------------------------------------
#define XB ((TOKENS * IN_F / 4) / 256)     // 32768
#define WB ((OUT_F * IN_F / 4) / 256)      // 16384

__global__ void prep_kernel(const float* __restrict__ x,
                            const int* __restrict__ Wq,
                            const float* __restrict__ scale,
                            const float* __restrict__ zero) {
    if (blockIdx.x < XB) {
        int i = blockIdx.x * 256 + threadIdx.x;          // one float4 of x
        float4 v = ((const float4*)x)[i];
        union { __half2 h[2]; uint2 u; } pk;
        pk.h[0] = __floats2half2_rn(v.x, v.y);
        pk.h[1] = __floats2half2_rn(v.z, v.w);
        int m  = i >> 10;                 // 1024 float4 per row
        int k  = (i & 1023) << 2;
        int mt = m >> 7, r = m & 127;
        int kc = k >> 6, c = k & 63;
        __half* dst = g_x + (size_t)(mt * NKC + kc) * A_CHUNK_HALFS + r * ROWH + c;
        *(uint2*)dst = pk.u;
    } else {
        int t = (blockIdx.x - XB) * 256 + threadIdx.x;   // 4 elements of W
        int idx = t << 2;
        int g = idx >> 6;
        int j = idx & 63;
        const int half_g = NGROUPS / 2;
        int pg = (g < half_g) ? g : (g - half_g);
        int4 q = *(const int4*)(Wq + (size_t)pg * GROUP + j);
        float z = zero[g], s = scale[g];
        float4 o;
        if (g < half_g) {
            o.x = ((float)((q.x >> 4) & 0xF) - z) * s;
            o.y = ((float)((q.y >> 4) & 0xF) - z) * s;
            o.z = ((float)((q.z >> 4) & 0xF) - z) * s;
            o.w = ((float)((q.w >> 4) & 0xF) - z) * s;
        } else {
            o.x = ((float)(q.x & 0xF) - z) * s;
            o.y = ((float)(q.y & 0xF) - z) * s;
            o.z = ((float)(q.z & 0xF) - z) * s;
            o.w = ((float)(q.w & 0xF) - z) * s;
        }
        union { __half2 h[2]; uint2 u; } pk;
        pk.h[0] = __floats2half2_rn(o.x, o.y);
        pk.h[1] = __floats2half2_rn(o.z, o.w);
        int n  = idx >> 12;
        int k  = idx & 4095;
        int nt = n >> 8, r = n & 255;
        int kc = k >> 6, c = k & 63;
        __half* dst = g_w + (size_t)(nt * NKC + kc) * B_CHUNK_HALFS + r * ROWH + c;
        *(uint2*)dst = pk.u;
    }
}

// ---------------------------------------------------------------------------
// sm_90-base async helpers (NO tcgen05 — ptxas target is sm_103, not sm_103a)
// ---------------------------------------------------------------------------
__device__ __forceinline__ void mbar_init(uint32_t mbar, uint32_t cnt) {
    asm volatile("mbarrier.init.shared.b64 [%0], %1;" :: "r"(mbar), "r"(cnt) : "memory");
}
__device__ __forceinline__ void mbar_arrive(uint32_t mbar) {
    asm volatile("mbarrier.arrive.release.cta.shared::cta.b64 _, [%0];"
                 :: "r"(mbar) : "memory");
}
__device__ __forceinline__ void mbar_expect_tx(uint32_t mbar, uint32_t bytes) {
    asm volatile("mbarrier.arrive.expect_tx.shared.b64 _, [%0], %1;"
                 :: "r"(mbar), "r"(bytes) : "memory");
}
__device__ __forceinline__ void mbar_wait(uint32_t mbar, uint32_t parity) {
    asm volatile(
        "{\n\t.reg .pred P;\n\t"
        "WL_%=:\n\t"
        "mbarrier.try_wait.parity.acquire.cta.shared::cta.b64 P, [%0], %1, 0x989680;\n\t"
        "@!P bra WL_%=;\n\t}"
        :: "r"(mbar), "r"(parity) : "memory");
}
__device__ __forceinline__ void bulk_g2s(uint32_t dst, const void* src,
                                         uint32_t bytes, uint32_t mbar) {
    asm volatile(
        "cp.async.bulk.shared::cluster.global.mbarrier::complete_tx::bytes "
        "[%0], [%1], %2, [%3];"
        :: "r"(dst), "l"(src), "r"(bytes), "r"(mbar) : "memory");
}
__device__ __forceinline__ void ldsm_x4(uint32_t* r, uint32_t addr) {
    asm volatile("ldmatrix.sync.aligned.m8n8.x4.shared.b16 {%0,%1,%2,%3}, [%4];"
                 : "=r"(r[0]), "=r"(r[1]), "=r"(r[2]), "=r"(r[3]) : "r"(addr));
}
__device__ __forceinline__ void mma16816(float* c, const uint32_t* a, const uint32_t* b) {
    asm volatile(
        "mma.sync.aligned.m16n8k16.row.col.f32.f16.f16.f32 "
        "{%0,%1,%2,%3}, {%4,%5,%6,%7}, {%8,%9}, {%0,%1,%2,%3};"
        : "+f"(c[0]), "+f"(c[1]), "+f"(c[2]), "+f"(c[3])
        : "r"(a[0]), "r"(a[1]), "r"(a[2]), "r"(a[3]), "r"(b[0]), "r"(b[1]));
}

// ---------------------------------------------------------------------------
// GEMM: out[M,N] = x[M,K] * W[N,K]^T + bias.  128x256x64 tile, fp16 mma.sync.
// Warp-specialized: warps 0-7 compute, warp 8 = bulk-TMA producer.
// full[s]: TMA tx barrier (count 1).  empty[s]: consumer arrivals (count 8).
// No __syncthreads in the mainloop — warps free-run and skew.
// ---------------------------------------------------------------------------
__global__ __launch_bounds__(288, 1)
void gemm_kernel(const float* __restrict__ bias, float* __restrict__ out) {
    extern __shared__ __align__(1024) char smem[];
    uint32_t sb = (uint32_t)__cvta_generic_to_shared(smem);
    const int tid  = threadIdx.x;
    const int lane = tid & 31;
    const int wid  = tid >> 5;
    const int bn0  = blockIdx.x * BN;
    const int bm0  = blockIdx.y * BM;

    // full[s] at sb + s*8 ; empty[s] at sb + 32 + s*8
    if (tid == 0) {
        #pragma unroll
        for (int s = 0; s < STAGES; s++) {
            mbar_init(sb + s * 8, 1);
            mbar_init(sb + 32 + s * 8, 8);
        }
        asm volatile("fence.proxy.async.shared::cta;" ::: "memory");
    }
    __syncthreads();

    if (wid == 8) {
        // ------------------- producer warp (one thread) -------------------
        if (lane == 0) {
            const __half* Asrc = g_x + (size_t)blockIdx.y * NKC * A_CHUNK_HALFS;
            const __half* Bsrc = g_w + (size_t)blockIdx.x * NKC * B_CHUNK_HALFS;
            for (int kc = 0; kc < NKC; kc++) {
                int s = kc % STAGES;
                if (kc >= STAGES)
                    mbar_wait(sb + 32 + s * 8, ((kc / STAGES) - 1) & 1);
                mbar_expect_tx(sb + s * 8, STAGE_BYTES);
                uint32_t st = sb + CTRL_BYTES + s * STAGE_BYTES;
                bulk_g2s(st,           Asrc + (size_t)kc * A_CHUNK_HALFS, A_BYTES, sb + s * 8);
                bulk_g2s(st + A_BYTES, Bsrc + (size_t)kc * B_CHUNK_HALFS, B_BYTES, sb + s * 8);
            }
        }
        return;
    }

    // ------------------------- compute warps 0-7 -------------------------
    const int wm = wid >> 2;              // 0..1  (64 rows)
    const int wn = wid & 3;               // 0..3  (64 cols)

    float acc[4][8][4];
    #pragma unroll
    for (int a = 0; a < 4; a++)
        #pragma unroll
        for (int b = 0; b < 8; b++)
            #pragma unroll
            for (int c = 0; c < 4; c++) acc[a][b][c] = 0.0f;

    const int a_row = (lane & 15);
    const int a_col = (lane >> 4) * 16;                   // bytes
    const int b_row = (lane & 7) + ((lane & 16) >> 1);
    const int b_col = ((lane >> 3) & 1) * 16;             // bytes

    for (int c = 0; c < NKC; c++) {
        int slot = c % STAGES;
        mbar_wait(sb + slot * 8, (c / STAGES) & 1);

        uint32_t aBase = sb + CTRL_BYTES + slot * STAGE_BYTES;
        uint32_t bBase = aBase + A_BYTES;

        #pragma unroll
        for (int ks = 0; ks < 4; ks++) {                  // 4 x k16 per BK=64
            uint32_t af[4][4];
            #pragma unroll
            for (int mt = 0; mt < 4; mt++)
                ldsm_x4(af[mt], aBase + (uint32_t)(wm * 64 + mt * 16 + a_row) * ROWB
                                + ks * 32 + a_col);
            uint32_t bf[8][2];
            #pragma unroll
            for (int bt = 0; bt < 4; bt++) {
                uint32_t r4[4];
                ldsm_x4(r4, bBase + (uint32_t)(wn * 64 + bt * 16 + b_row) * ROWB
                             + ks * 32 + b_col);
                bf[2 * bt][0] = r4[0]; bf[2 * bt][1] = r4[1];
                bf[2 * bt + 1][0] = r4[2]; bf[2 * bt + 1][1] = r4[3];
            }
            #pragma unroll
            for (int mt = 0; mt < 4; mt++)
                #pragma unroll
                for (int nt = 0; nt < 8; nt++)
                    mma16816(acc[mt][nt], af[mt], bf[nt]);
        }

        // this warp is done reading slot: signal producer
        if (lane == 0) mbar_arrive(sb + 32 + slot * 8);
    }

    // Epilogue: +bias, float2 stores
    const int lr = lane >> 2;
    const int lc = lane & 3;
    #pragma unroll
    for (int mt = 0; mt < 4; mt++) {
        #pragma unroll
        for (int nt = 0; nt < 8; nt++) {
            int row = bm0 + wm * 64 + mt * 16 + lr;
            int col = bn0 + wn * 64 + nt * 8 + lc * 2;
            float b0 = __ldg(&bias[col]), b1 = __ldg(&bias[col + 1]);
            *(float2*)&out[(size_t)row * OUT_F + col] =
                make_float2(acc[mt][nt][0] + b0, acc[mt][nt][1] + b1);
            *(float2*)&out[(size_t)(row + 8) * OUT_F + col] =
                make_float2(acc[mt][nt][2] + b0, acc[mt][nt][3] + b1);
        }
    }
}

// ---------------------------------------------------------------------------
// Launch
// ---------------------------------------------------------------------------
extern "C" void kernel_launch(void* const* d_in, const int* in_sizes, int n_in,
                              void* d_out, int out_size) {
    const float* x     = (const float*)d_in[0];
    const int*   Wq    = (const int*)d_in[1];
    const float* scale = (const float*)d_in[2];
    const float* zero  = (const float*)d_in[3];
    const float* bias  = (const float*)d_in[4];
    float* out = (float*)d_out;

    prep_kernel<<<XB + WB, 256>>>(x, Wq, scale, zero);

    cudaFuncSetAttribute(gemm_kernel, cudaFuncAttributeMaxDynamicSharedMemorySize, SMEM_TOTAL);
    dim3 grid(OUT_F / BN, TOKENS / BM);   // (16, 64)
    gemm_kernel<<<grid, 288, SMEM_TOTAL>>>(bias, out);
}